// round 8
// baseline (speedup 1.0000x reference)
#include <cuda_runtime.h>

#define NIMG 8
#define IMG  512
#define NPIX (IMG * IMG)

__device__ float g_min_a[NIMG * NPIX];
__device__ float g_min_b[NIMG * NPIX];
__device__ float g_max_a[NIMG * NPIX];
__device__ float g_max_b[NIMG * NPIX];

struct HeadConsts {
    float A2[32][18][2];
    float cb2[32][2];
    float w2[32];
    float Amin[32][9];
    float Amax[32][9];
    float Bsum[32][9];
    float b1[32];
    float b2;
};
__device__ HeadConsts HC;

template <bool M> __device__ __forceinline__ float xop(float a, float b) {
    return M ? fminf(a, b) : fmaxf(a, b);
}
template <bool M> __device__ __forceinline__ float xop3(float a, float b, float c) {
    return xop<M>(a, xop<M>(b, c));
}
__device__ __forceinline__ float fmin3(float a, float b, float c) { return fminf(a, fminf(b, c)); }

__device__ __forceinline__ unsigned long long pk2(float lo, float hi) {
    unsigned long long r;
    asm("mov.b64 %0, {%1, %2};" : "=l"(r) : "f"(lo), "f"(hi));
    return r;
}
__device__ __forceinline__ void upk2(unsigned long long v, float& lo, float& hi) {
    asm("mov.b64 {%0, %1}, %2;" : "=f"(lo), "=f"(hi) : "l"(v));
}
__device__ __forceinline__ unsigned long long fma2(unsigned long long a, unsigned long long b,
                                                   unsigned long long c) {
    unsigned long long d;
    asm("fma.rn.f32x2 %0, %1, %2, %3;" : "=l"(d) : "l"(a), "l"(b), "l"(c));
    return d;
}

// ---- fold weights ----------------------------------------------------------
__global__ void prep_kernel(const float* __restrict__ w0, const float* __restrict__ b0,
                            const float* __restrict__ w1, const float* __restrict__ b1,
                            const float* __restrict__ w2, const float* __restrict__ b2) {
    int id = threadIdx.x;
    if (id < 288) {
        int j = id / 9, t = id % 9;
        float amin = 0.f, amax = 0.f, bs = 0.f;
        for (int c = 0; c < 8; c++) {
            float w = w1[j * 72 + c * 9 + t];
            float w0c = w0[c];
            if (w0c >= 0.f) amin += w * w0c; else amax += w * w0c;
            bs += w * (65536.f * b0[c]);
        }
        HC.Amin[j][t] = amin; HC.Amax[j][t] = amax; HC.Bsum[j][t] = bs;
        HC.A2[j][t][0] = amin;     HC.A2[j][t][1] = amin;
        HC.A2[j][9 + t][0] = amax; HC.A2[j][9 + t][1] = amax;
    }
    if (id < 32) {
        int j = id;
        float cb = b1[j];
        for (int c = 0; c < 8; c++) {
            float bc = 65536.f * b0[c];
            for (int t = 0; t < 9; t++) cb += w1[j * 72 + c * 9 + t] * bc;
        }
        HC.cb2[j][0] = cb; HC.cb2[j][1] = cb;
        HC.w2[j] = w2[j];
        HC.b1[j] = b1[j];
    }
    if (id == 0) HC.b2 = b2[0];
}

// ---- standalone round (R4 config, 6-op hpool): 16 rows/thread, 8 out rows --
template <bool M>
__device__ __forceinline__ float4 hpool16(float4 v, int r, int p, int warp, int lane,
                                          const float* eL, const float* eR, float BND) {
    float left  = __shfl_up_sync(0xffffffffu, v.w, 1);
    float right = __shfl_down_sync(0xffffffffu, v.x, 1);
    if (lane == 0)  left  = (warp == 0) ? BND : eR[((p * 4) + warp - 1) * 16 + r];
    if (lane == 31) right = (warp == 3) ? BND : eL[((p * 4) + warp + 1) * 16 + r];
    float mxy = xop<M>(v.x, v.y), mzw = xop<M>(v.z, v.w);
    float4 h;
    h.x = xop<M>(left, mxy); h.y = xop<M>(mxy, v.z);
    h.z = xop<M>(v.y, mzw);  h.w = xop<M>(mzw, right);
    return h;
}

template <bool M>
__device__ __forceinline__ void do_round(const float* __restrict__ s, float* __restrict__ dp,
                                         float* eL, float* eR) {
    const int tid = threadIdx.x;
    const int warp = tid >> 5, lane = tid & 31;
    const int tile = blockIdx.x;
    const int r0 = tile * 8 - 4;
    const int col = warp * 128 + lane * 4;
    const float BND = M ? __int_as_float(0x7F800000) : __int_as_float(0xFF800000);

    float4 d[16];
#pragma unroll
    for (int i = 0; i < 16; i++) {
        int rr = r0 + i;
        if (rr >= 0 && rr < IMG) d[i] = *(const float4*)(s + (size_t)rr * IMG + col);
        else                     d[i] = make_float4(BND, BND, BND, BND);
    }

#pragma unroll
    for (int it = 0; it < 4; it++) {
        const int p = it & 1;
        if (lane == 0) {
#pragma unroll
            for (int i = 0; i < 16; i++) eL[((p * 4) + warp) * 16 + i] = d[i].x;
        } else if (lane == 31) {
#pragma unroll
            for (int i = 0; i < 16; i++) eR[((p * 4) + warp) * 16 + i] = d[i].w;
        }
        __syncthreads();

        const int lo = it + 1, hi = 14 - it;
        float4 hp = hpool16<M>(d[lo - 1], lo - 1, p, warp, lane, eL, eR, BND);
        float4 hc = hpool16<M>(d[lo],     lo,     p, warp, lane, eL, eR, BND);
#pragma unroll
        for (int r = lo; r <= hi; r++) {
            float4 hn = hpool16<M>(d[r + 1], r + 1, p, warp, lane, eL, eR, BND);
            d[r].x += xop3<M>(hp.x, hc.x, hn.x); d[r].y += xop3<M>(hp.y, hc.y, hn.y);
            d[r].z += xop3<M>(hp.z, hc.z, hn.z); d[r].w += xop3<M>(hp.w, hc.w, hn.w);
            hp = hc; hc = hn;
        }
    }

#pragma unroll
    for (int i = 4; i < 12; i++) {
        int rr = r0 + i;
        *(float4*)(dp + (size_t)rr * IMG + col) = d[i];
    }
}

__global__ __launch_bounds__(128) void round_kernel(const float* __restrict__ srcMin,
                                                    const float* __restrict__ srcMax,
                                                    float* __restrict__ dstMin,
                                                    float* __restrict__ dstMax) {
    __shared__ float eL[2 * 4 * 16];
    __shared__ float eR[2 * 4 * 16];
    const size_t ib = (size_t)blockIdx.y * NPIX;
    if (blockIdx.z == 0) do_round<true>(srcMin + ib, dstMin + ib, eL, eR);
    else                 do_round<false>(srcMax + ib, dstMax + ib, eL, eR);
}

// ---- fused last round + head: 14 rows/thread, head over middle 4 rows ------
template <bool M>
__device__ __forceinline__ float4 hpool14(float4 v, int r, int p, int warp, int lane,
                                          const float* eL, const float* eR, float BND) {
    float left  = __shfl_up_sync(0xffffffffu, v.w, 1);
    float right = __shfl_down_sync(0xffffffffu, v.x, 1);
    if (lane == 0)  left  = (warp == 0) ? BND : eR[((p * 4) + warp - 1) * 14 + r];
    if (lane == 31) right = (warp == 3) ? BND : eL[((p * 4) + warp + 1) * 14 + r];
    float mxy = xop<M>(v.x, v.y), mzw = xop<M>(v.z, v.w);
    float4 h;
    h.x = xop<M>(left, mxy); h.y = xop<M>(mxy, v.z);
    h.z = xop<M>(v.y, mzw);  h.w = xop<M>(mzw, right);
    return h;
}

template <bool M, int IT>
__device__ __forceinline__ void pass14(float4 (&d)[14], int warp, int lane,
                                       const float* eL, const float* eR, float BND) {
    const int p = IT & 1;
    const int lo = IT + 1, hi = 12 - IT;
    float4 hp = hpool14<M>(d[lo - 1], lo - 1, p, warp, lane, eL, eR, BND);
    float4 hc = hpool14<M>(d[lo],     lo,     p, warp, lane, eL, eR, BND);
#pragma unroll
    for (int r = lo; r <= hi; r++) {
        float4 hn = hpool14<M>(d[r + 1], r + 1, p, warp, lane, eL, eR, BND);
        d[r].x += xop3<M>(hp.x, hc.x, hn.x); d[r].y += xop3<M>(hp.y, hc.y, hn.y);
        d[r].z += xop3<M>(hp.z, hc.z, hn.z); d[r].w += xop3<M>(hp.w, hc.w, hn.w);
        hp = hc; hc = hn;
    }
}

template <int IT>
__device__ __forceinline__ void round_step(float4 (&dmn)[14], float4 (&dmx)[14],
                                           int warp, int lane,
                                           float* eLmn, float* eRmn, float* eLmx, float* eRmx) {
    const int p = IT & 1;
    const float PINF = __int_as_float(0x7F800000);
    if (lane == 0) {
#pragma unroll
        for (int i = 0; i < 14; i++) {
            eLmn[((p * 4) + warp) * 14 + i] = dmn[i].x;
            eLmx[((p * 4) + warp) * 14 + i] = dmx[i].x;
        }
    } else if (lane == 31) {
#pragma unroll
        for (int i = 0; i < 14; i++) {
            eRmn[((p * 4) + warp) * 14 + i] = dmn[i].w;
            eRmx[((p * 4) + warp) * 14 + i] = dmx[i].w;
        }
    }
    __syncthreads();
    pass14<true, IT>(dmn, warp, lane, eLmn, eRmn, PINF);
    pass14<false, IT>(dmx, warp, lane, eLmx, eRmx, -PINF);
}

__global__ __launch_bounds__(128) void fused_kernel(const float* __restrict__ srcMin,
                                                    const float* __restrict__ srcMax,
                                                    float* __restrict__ finMin,
                                                    float* __restrict__ finMax,
                                                    float* __restrict__ out) {
    __shared__ float eLmn[2 * 4 * 14], eRmn[2 * 4 * 14];
    __shared__ float eLmx[2 * 4 * 14], eRmx[2 * 4 * 14];
    __shared__ unsigned long long A2s[32][18];
    __shared__ unsigned long long cb2s[32];
    __shared__ float w2s[32];
    const int tid = threadIdx.x;
    const int warp = tid >> 5, lane = tid & 31;
    {
        const unsigned long long* A2g = (const unsigned long long*)(&HC.A2[0][0][0]);
        for (int i = tid; i < 32 * 18; i += 128) ((unsigned long long*)A2s)[i] = A2g[i];
        if (tid < 32) {
            cb2s[tid] = ((const unsigned long long*)HC.cb2)[tid];
            w2s[tid] = HC.w2[tid];
        }
    }
    const int img = blockIdx.y, tile = blockIdx.x;
    const int r0 = tile * 4 - 5;
    const int col = tid * 4;
    const float PINF = __int_as_float(0x7F800000);
    const float* smn = srcMin + (size_t)img * NPIX;
    const float* smx = srcMax + (size_t)img * NPIX;

    float4 dmn[14], dmx[14];
#pragma unroll
    for (int i = 0; i < 14; i++) {
        int rr = r0 + i;
        if (rr >= 0 && rr < IMG) {
            dmn[i] = *(const float4*)(smn + (size_t)rr * IMG + col);
            dmx[i] = *(const float4*)(smx + (size_t)rr * IMG + col);
        } else {
            dmn[i] = make_float4(PINF, PINF, PINF, PINF);
            dmx[i] = make_float4(-PINF, -PINF, -PINF, -PINF);
        }
    }

    // 4 pooling iterations (iterations 13..16 of the recurrence)
    round_step<0>(dmn, dmx, warp, lane, eLmn, eRmn, eLmx, eRmx);
    round_step<1>(dmn, dmx, warp, lane, eLmn, eRmn, eLmx, eRmx);
    round_step<2>(dmn, dmx, warp, lane, eLmn, eRmn, eLmx, eRmx);
    round_step<3>(dmn, dmx, warp, lane, eLmn, eRmn, eLmx, eRmx);

    // store final fields for this tile's 4 output rows (for border kernel)
    float* fmn = finMin + (size_t)img * NPIX;
    float* fmx = finMax + (size_t)img * NPIX;
#pragma unroll
    for (int i = 5; i < 9; i++) {
        int rr = r0 + i;
        *(float4*)(fmn + (size_t)rr * IMG + col) = dmn[i];
        *(float4*)(fmx + (size_t)rr * IMG + col) = dmx[i];
    }

    // warp-edge finals (rows local 4..9) for head packs; p=0 buffers are free
    if (lane == 0) {
#pragma unroll
        for (int k = 0; k < 6; k++) {
            eLmn[warp * 14 + k] = dmn[4 + k].x;
            eLmx[warp * 14 + k] = dmx[4 + k].x;
        }
    } else if (lane == 31) {
#pragma unroll
        for (int k = 0; k < 6; k++) {
            eRmn[warp * 14 + k] = dmn[4 + k].w;
            eRmx[warp * 14 + k] = dmx[4 + k].w;
        }
    }
    __syncthreads();

    // packed horizontal tap pairs for 6 final rows
    unsigned long long pmn[6][5], pmx[6][5];
#pragma unroll
    for (int k = 0; k < 6; k++) {
        float4 v = dmn[4 + k];
        float L = __shfl_up_sync(0xffffffffu, v.w, 1);
        float R = __shfl_down_sync(0xffffffffu, v.x, 1);
        if (lane == 0)  L = (warp == 0) ? PINF : eRmn[(warp - 1) * 14 + k];
        if (lane == 31) R = (warp == 3) ? PINF : eLmn[(warp + 1) * 14 + k];
        pmn[k][0] = pk2(L, v.x);   pmn[k][1] = pk2(v.x, v.y);
        pmn[k][2] = pk2(v.y, v.z); pmn[k][3] = pk2(v.z, v.w);
        pmn[k][4] = pk2(v.w, R);
        v = dmx[4 + k];
        L = __shfl_up_sync(0xffffffffu, v.w, 1);
        R = __shfl_down_sync(0xffffffffu, v.x, 1);
        if (lane == 0)  L = (warp == 0) ? -PINF : eRmx[(warp - 1) * 14 + k];
        if (lane == 31) R = (warp == 3) ? -PINF : eLmx[(warp + 1) * 14 + k];
        pmx[k][0] = pk2(L, v.x);   pmx[k][1] = pk2(v.x, v.y);
        pmx[k][2] = pk2(v.y, v.z); pmx[k][3] = pk2(v.z, v.w);
        pmx[k][4] = pk2(v.w, R);
    }

    // head: 4 rows x 4 cols per thread, 2 pixel-pairs, packed f32x2
    float a0x[4] = {0.f, 0.f, 0.f, 0.f}, a0y[4] = {0.f, 0.f, 0.f, 0.f};
    float a1x[4] = {0.f, 0.f, 0.f, 0.f}, a1y[4] = {0.f, 0.f, 0.f, 0.f};
#pragma unroll 2
    for (int j = 0; j < 32; j++) {
        unsigned long long cb = cb2s[j];
        unsigned long long u0[4], u1[4];
#pragma unroll
        for (int ry = 0; ry < 4; ry++) { u0[ry] = cb; u1[ry] = cb; }
#pragma unroll
        for (int k = 0; k < 9; k++) {
            const int kh = k / 3, kw = k % 3;
            unsigned long long a = A2s[j][k];
#pragma unroll
            for (int ry = 0; ry < 4; ry++) {
                u0[ry] = fma2(a, pmn[ry + kh][kw],     u0[ry]);
                u1[ry] = fma2(a, pmn[ry + kh][kw + 2], u1[ry]);
            }
        }
#pragma unroll
        for (int k = 0; k < 9; k++) {
            const int kh = k / 3, kw = k % 3;
            unsigned long long a = A2s[j][9 + k];
#pragma unroll
            for (int ry = 0; ry < 4; ry++) {
                u0[ry] = fma2(a, pmx[ry + kh][kw],     u0[ry]);
                u1[ry] = fma2(a, pmx[ry + kh][kw + 2], u1[ry]);
            }
        }
        float w = w2s[j], lo, hi;
#pragma unroll
        for (int ry = 0; ry < 4; ry++) {
            upk2(u0[ry], lo, hi);
            a0x[ry] = fmaf(w, fmaxf(lo, 0.f), a0x[ry]);
            a0y[ry] = fmaf(w, fmaxf(hi, 0.f), a0y[ry]);
            upk2(u1[ry], lo, hi);
            a1x[ry] = fmaf(w, fmaxf(lo, 0.f), a1x[ry]);
            a1y[ry] = fmaf(w, fmaxf(hi, 0.f), a1y[ry]);
        }
    }

    const float b2v = HC.b2;
    float* op = out + (size_t)img * NPIX;
#pragma unroll
    for (int ry = 0; ry < 4; ry++) {
        float4 o = make_float4(b2v + a0x[ry], b2v + a0y[ry], b2v + a1x[ry], b2v + a1y[ry]);
        *(float4*)(op + (size_t)(tile * 4 + ry) * IMG + col) = o;
    }
}

// ---- head border: exact tap-gated recompute for the 1-pixel frame ----------
__global__ void head_border_kernel(const float* __restrict__ gmin,
                                   const float* __restrict__ gmax,
                                   float* __restrict__ out) {
    const int img = blockIdx.y;
    const int bi = blockIdx.x * blockDim.x + threadIdx.x;
    if (bi >= 2044) return;
    int x, y;
    if (bi < 512)        { y = 0;   x = bi; }
    else if (bi < 1024)  { y = 511; x = bi - 512; }
    else if (bi < 1534)  { x = 0;   y = bi - 1024 + 1; }
    else                 { x = 511; y = bi - 1534 + 1; }

    const float* gm = gmin + (size_t)img * NPIX;
    const float* gx = gmax + (size_t)img * NPIX;

    float vmn[9], vmx[9];
    bool valid[9];
#pragma unroll
    for (int k = 0; k < 9; k++) {
        int ty = y + k / 3 - 1, tx = x + k % 3 - 1;
        valid[k] = (ty >= 0 && ty < IMG && tx >= 0 && tx < IMG);
        size_t off = (size_t)min(max(ty, 0), IMG - 1) * IMG + (size_t)min(max(tx, 0), IMG - 1);
        vmn[k] = valid[k] ? gm[off] : 0.f;
        vmx[k] = valid[k] ? gx[off] : 0.f;
    }
    float acc = 0.f;
    for (int j = 0; j < 32; j++) {
        float u = HC.b1[j];
#pragma unroll
        for (int k = 0; k < 9; k++) {
            if (valid[k])
                u += HC.Amin[j][k] * vmn[k] + HC.Amax[j][k] * vmx[k] + HC.Bsum[j][k];
        }
        acc = fmaf(HC.w2[j], fmaxf(u, 0.f), acc);
    }
    out[(size_t)img * NPIX + (size_t)y * IMG + x] = HC.b2 + acc;
}

// ---------------------------------------------------------------------------
extern "C" void kernel_launch(void* const* d_in, const int* in_sizes, int n_in,
                              void* d_out, int out_size) {
    const float* x  = (const float*)d_in[0];
    const float* w0 = (const float*)d_in[1];
    const float* b0 = (const float*)d_in[2];
    const float* w1 = (const float*)d_in[3];
    const float* b1 = (const float*)d_in[4];
    const float* w2 = (const float*)d_in[5];
    const float* b2 = (const float*)d_in[6];
    float* out = (float*)d_out;

    static float *pMinA = nullptr, *pMinB = nullptr, *pMaxA = nullptr, *pMaxB = nullptr;
    if (!pMinA) {
        cudaGetSymbolAddress((void**)&pMinA, g_min_a);
        cudaGetSymbolAddress((void**)&pMinB, g_min_b);
        cudaGetSymbolAddress((void**)&pMaxA, g_max_a);
        cudaGetSymbolAddress((void**)&pMaxB, g_max_b);
    }

    prep_kernel<<<1, 288>>>(w0, b0, w1, b1, w2, b2);

    dim3 rblk(128);
    dim3 rgrd(IMG / 8, NIMG, 2);
    round_kernel<<<rgrd, rblk>>>(x,     x,     pMinA, pMaxA);   // iters 1-4
    round_kernel<<<rgrd, rblk>>>(pMinA, pMaxA, pMinB, pMaxB);   // iters 5-8
    round_kernel<<<rgrd, rblk>>>(pMinB, pMaxB, pMinA, pMaxA);   // iters 9-12

    dim3 fgrd(IMG / 4, NIMG);
    fused_kernel<<<fgrd, rblk>>>(pMinA, pMaxA, pMinB, pMaxB, out);  // iters 13-16 + head

    head_border_kernel<<<dim3(16, NIMG), 128>>>(pMinB, pMaxB, out);
}